// round 5
// baseline (speedup 1.0000x reference)
#include <cuda_runtime.h>
#include <cstdint>
#include <cstddef>

// ---------------------------------------------------------------------------
// 2-layer LSTM (T=512, B=4096, D=64, H=70) + MLP head.
// R4: 384 threads (3 warps/SMSP) to hide LDS latency; pair-interleaved gate
//     layout so all activations run packed f32x2; packed FMA-only
//     sigmoid/tanh (exp2 bit-trick + Newton rcp on [1,2]).
// ---------------------------------------------------------------------------

#define TT   512
#define BB   4096
#define DD   64
#define HH   70
#define GP   288          // padded gate cols = 12 warps * 24
#define BC   32           // batch rows per block
#define NBLK (BB / BC)    // 128 blocks
#define NTHR 384          // 12 warps
#define NW   12

typedef unsigned long long u64;

// scratch: h0 sequence [T][H][B], final h1 [H][B]
__device__ float g_h0[(size_t)TT * HH * BB];
__device__ float g_h1[HH * BB];

#define FMA2A(d, a, b) \
    asm("fma.rn.f32x2 %0, %1, %2, %0;" : "+l"(d) : "l"(a), "l"(b))
#define FMA2(d, a, b, c) \
    asm("fma.rn.f32x2 %0, %1, %2, %3;" : "=l"(d) : "l"(a), "l"(b), "l"(c))
#define MUL2(d, a, b) \
    asm("mul.rn.f32x2 %0, %1, %2;" : "=l"(d) : "l"(a), "l"(b))
#define ADD2(d, a, b) \
    asm("add.rn.f32x2 %0, %1, %2;" : "=l"(d) : "l"(a), "l"(b))

__device__ __forceinline__ u64 dup2(float v) {
    u64 r;
    unsigned int u = __float_as_uint(v);
    asm("mov.b64 %0, {%1,%2};" : "=l"(r) : "r"(u), "r"(u));
    return r;
}
__device__ __forceinline__ u64 pack2(unsigned int lo, unsigned int hi) {
    u64 r;
    asm("mov.b64 %0, {%1,%2};" : "=l"(r) : "r"(lo), "r"(hi));
    return r;
}
__device__ __forceinline__ void unpack2(u64 v, unsigned int& lo, unsigned int& hi) {
    asm("mov.b64 {%0,%1}, %2;" : "=r"(lo), "=r"(hi) : "l"(v));
}

// packed constants (both halves identical, by bit pattern)
#define PKC(x) ((((u64)(x)) << 32) | (u64)(x))
__device__ __forceinline__ u64 C_RK()    { return PKC(0x4B400000u); } // 12582912
__device__ __forceinline__ u64 C_NRK()   { return PKC(0xCB400000u); } // -12582912
__device__ __forceinline__ u64 C_ONE()   { return PKC(0x3F800000u); }
__device__ __forceinline__ u64 C_NONE()  { return PKC(0xBF800000u); }
__device__ __forceinline__ u64 C_HALF()  { return PKC(0x3F000000u); }
__device__ __forceinline__ u64 C_TWO()   { return PKC(0x40000000u); }
__device__ __forceinline__ u64 C_ABS()   { return PKC(0x7FFFFFFFu); }
__device__ __forceinline__ u64 C_SGN()   { return PKC(0x80000000u); }
// tanh core scale: -2*log2(e) = -2.88539008  (bits 0xC038AA3B)
__device__ __forceinline__ u64 C_KT()    { return PKC(0xC038AA3Bu); }
// sigmoid core scale: -log2(e) = -1.44269504 (bits 0xBFB8AA3B)
__device__ __forceinline__ u64 C_KS()    { return PKC(0xBFB8AA3Bu); }
// rcp linear seed on [1,2]: x0 = 1.45711 - 0.5*d
__device__ __forceinline__ u64 C_RA()    { return PKC(0x3FBA8281u); } // 1.45711
__device__ __forceinline__ u64 C_NRB()   { return PKC(0xBF000000u); } // -0.5
// exp2 poly coefficients
__device__ __forceinline__ u64 C_P6() { return PKC(0x392188D5u); } // 1.54035304e-4
__device__ __forceinline__ u64 C_P5() { return PKC(0x3AAEC087u); } // 1.33335581e-3
__device__ __forceinline__ u64 C_P4() { return PKC(0x3C1D94FCu); } // 9.61812911e-3
__device__ __forceinline__ u64 C_P3() { return PKC(0x3D635766u); } // 5.55041087e-2
__device__ __forceinline__ u64 C_P2() { return PKC(0x3E75FDF0u); } // 2.40226507e-1
__device__ __forceinline__ u64 C_P1() { return PKC(0x3F317218u); } // 6.93147181e-1

// packed tanh-core: tc(a) = (1 - e)/(1 + e), e = 2^(ks*a), a >= 0 both halves.
// ks < 0 so exp2 arg <= 0, e in (0,1], denom in [1,2].
__device__ __forceinline__ u64 tc2(u64 a2, u64 ks) {
    u64 y2; MUL2(y2, a2, ks);
    u64 t2; ADD2(t2, y2, C_RK());
    unsigned int r0, r1; unpack2(t2, r0, r1);
    int s0 = ((int)r0) << 23;
    int s1 = ((int)r1) << 23;
    s0 = max(s0, (int)0xC1000000);   // keep exponent add in normal range
    s1 = max(s1, (int)0xC1000000);
    u64 u2; ADD2(u2, t2, C_NRK());
    u64 f2; FMA2(f2, u2, C_NONE(), y2);
    u64 p = C_P6();
    FMA2(p, p, f2, C_P5());
    FMA2(p, p, f2, C_P4());
    FMA2(p, p, f2, C_P3());
    FMA2(p, p, f2, C_P2());
    FMA2(p, p, f2, C_P1());
    FMA2(p, p, f2, C_ONE());
    unsigned int p0, p1; unpack2(p, p0, p1);
    u64 e2 = pack2(p0 + (unsigned int)s0, p1 + (unsigned int)s1);
    u64 d2; ADD2(d2, e2, C_ONE());
    u64 nd2 = d2 ^ C_SGN();
    u64 x; FMA2(x, d2, C_NRB(), C_RA());       // linear seed
    u64 t; FMA2(t, nd2, x, C_TWO()); MUL2(x, x, t);
    FMA2(t, nd2, x, C_TWO()); MUL2(x, x, t);   // 2 Newton iters
    u64 num; FMA2(num, e2, C_NONE(), C_ONE());
    u64 r; MUL2(r, num, x);
    return r;
}
__device__ __forceinline__ u64 tanh2p(u64 x2) {
    u64 a2 = x2 & C_ABS();
    u64 t = tc2(a2, C_KT());
    return t | (x2 & C_SGN());
}
__device__ __forceinline__ u64 sig2p(u64 x2) {
    u64 a2 = x2 & C_ABS();
    u64 t = tc2(a2, C_KS());
    t |= (x2 & C_SGN());
    u64 r; FMA2(r, t, C_HALF(), C_HALF());
    return r;
}

// scalar helpers for head kernel
__device__ __forceinline__ float fexp2s(float y) {
    y = fminf(fmaxf(y, -28.0f), 28.0f);
    float t = __fadd_rn(y, 12582912.0f);
    int   n = __float_as_int(t) - 0x4B400000;
    float f = __fsub_rn(y, __fsub_rn(t, 12582912.0f));
    float p =            1.54035304e-4f;
    p = __fmaf_rn(p, f,  1.33335581e-3f);
    p = __fmaf_rn(p, f,  9.61812911e-3f);
    p = __fmaf_rn(p, f,  5.55041087e-2f);
    p = __fmaf_rn(p, f,  2.40226507e-1f);
    p = __fmaf_rn(p, f,  6.93147181e-1f);
    p = __fmaf_rn(p, f,  1.0f);
    return __int_as_float(__float_as_int(p) + (n << 23));
}
__device__ __forceinline__ float frcps(float a) {
    float x = __int_as_float(0x7EF311C3 - __float_as_int(a));
    x = x * __fmaf_rn(-a, x, 2.0f);
    x = x * __fmaf_rn(-a, x, 2.0f);
    x = x * __fmaf_rn(-a, x, 2.0f);
    return x;
}
__device__ __forceinline__ float fsigmoids(float x) {
    return frcps(1.0f + fexp2s(x * -1.44269504f));
}

// column mapping: gate-major row j -> pair-interleaved column
__device__ __forceinline__ int gcol(int j) {
    int g = j / HH, n = j - g * HH;
    return 8 * (n >> 1) + 2 * g + (n & 1);
}

template <int KA, bool IN_TBK, bool WRITE_SEQ, bool FINAL_OUT>
__global__ void __launch_bounds__(NTHR, 1)
lstm_layer(const float* __restrict__ in_seq,
           const float* __restrict__ Wih, const float* __restrict__ Whh,
           const float* __restrict__ bih, const float* __restrict__ bhh,
           float* __restrict__ seq_out, float* __restrict__ fin_out)
{
    extern __shared__ float sm[];
    float* Wa   = sm;                          // [KA][GP]
    float* Wb   = Wa + KA * GP;                // [HH][GP]
    float* bias = Wb + HH * GP;                // [GP]
    u64* inb2 = reinterpret_cast<u64*>(bias + GP);   // [KA][33]
    u64* hb2  = inb2 + KA * 33;                      // [HH][33]

    const int tid  = threadIdx.x;
    const int lane = tid & 31;
    const int w    = tid >> 5;
    const int row0 = blockIdx.x * BC;

    for (int i = tid; i < (KA + HH) * GP + GP; i += NTHR) sm[i] = 0.f;
    {
        float* hf = reinterpret_cast<float*>(hb2);
        for (int i = tid; i < HH * 33 * 2; i += NTHR) hf[i] = 0.f;
    }
    __syncthreads();

    for (int idx = tid; idx < 4 * HH * KA; idx += NTHR) {
        int j = idx / KA, k = idx - j * KA;
        Wa[k * GP + gcol(j)] = Wih[idx];
    }
    for (int idx = tid; idx < 4 * HH * HH; idx += NTHR) {
        int j = idx / HH, k = idx - j * HH;
        Wb[k * GP + gcol(j)] = Whh[idx];
    }
    for (int j = tid; j < 4 * HH; j += NTHR)
        bias[gcol(j)] = bih[j] + bhh[j];
    __syncthreads();

    const ulonglong2* bias2 =
        reinterpret_cast<const ulonglong2*>(bias + w * 24);

    u64 creg[3] = {0ull, 0ull, 0ull};   // packed c for 3 unit-pairs

    for (int t = 0; t < TT; t++) {
        // ---- stage input tile (duplicated pairs)
        if (!IN_TBK) {
            // in_seq [T][B][KA], KA=64
#pragma unroll
            for (int ii = 0; ii < (BC * KA + NTHR - 1) / NTHR; ii++) {
                int idx = tid + ii * NTHR;
                if (idx < BC * KA) {
                    int r = idx >> 6, k = idx & 63;
                    inb2[k * 33 + r] =
                        dup2(in_seq[((size_t)t * BB + row0 + r) * KA + k]);
                }
            }
        } else {
            // in_seq [T][KA][B], KA=70
#pragma unroll
            for (int ii = 0; ii < (BC * KA + NTHR - 1) / NTHR; ii++) {
                int idx = tid + ii * NTHR;
                if (idx < BC * KA) {
                    int k = idx >> 5, r = idx & 31;
                    inb2[k * 33 + r] =
                        dup2(in_seq[((size_t)t * KA + k) * BB + row0 + r]);
                }
            }
        }
        __syncthreads();

        // ---- gates GEMM: warp w -> 24 cols (3 unit pairs), 32 batch rows
        u64 acc[12];
#pragma unroll
        for (int q = 0; q < 6; q++) {
            ulonglong2 b2 = bias2[q];
            acc[2 * q] = b2.x;
            acc[2 * q + 1] = b2.y;
        }
        {
            const u64* xp = inb2 + lane;
            const float* Wrow = Wa + w * 24;
#pragma unroll 2
            for (int k = 0; k < KA; k++) {
                u64 x2 = xp[k * 33];
                const ulonglong2* Wk =
                    reinterpret_cast<const ulonglong2*>(Wrow + k * GP);
#pragma unroll
                for (int q = 0; q < 6; q++) {
                    ulonglong2 ww = Wk[q];
                    FMA2A(acc[2 * q], ww.x, x2);
                    FMA2A(acc[2 * q + 1], ww.y, x2);
                }
            }
        }
        {
            const u64* hp = hb2 + lane;
            const float* Wrow = Wb + w * 24;
#pragma unroll 2
            for (int k = 0; k < HH; k++) {
                u64 x2 = hp[k * 33];
                const ulonglong2* Wk =
                    reinterpret_cast<const ulonglong2*>(Wrow + k * GP);
#pragma unroll
                for (int q = 0; q < 6; q++) {
                    ulonglong2 ww = Wk[q];
                    FMA2A(acc[2 * q], ww.x, x2);
                    FMA2A(acc[2 * q + 1], ww.y, x2);
                }
            }
        }
        __syncthreads();   // all GEMM reads of hb2 done before overwrite

        // ---- packed cell update; pair p holds units (2P, 2P+1), P = 3w+p
#pragma unroll
        for (int p = 0; p < 3; p++) {
            int P  = 3 * w + p;
            u64 i2 = sig2p (acc[4 * p + 0]);
            u64 f2 = sig2p (acc[4 * p + 1]);
            u64 g2 = tanh2p(acc[4 * p + 2]);
            u64 o2 = sig2p (acc[4 * p + 3]);
            u64 ig; MUL2(ig, i2, g2);
            u64 c2; FMA2(c2, f2, creg[p], ig);
            creg[p] = c2;
            u64 th = tanh2p(c2);
            u64 h2; MUL2(h2, o2, th);
            unsigned int hlo, hhi; unpack2(h2, hlo, hhi);
            int n0 = 2 * P, n1 = 2 * P + 1;
            if (n0 < HH) {
                float h = __uint_as_float(hlo);
                hb2[n0 * 33 + lane] = dup2(h);
                if (WRITE_SEQ)
                    seq_out[((size_t)t * HH + n0) * BB + row0 + lane] = h;
                if (FINAL_OUT && t == TT - 1)
                    fin_out[n0 * BB + row0 + lane] = h;
            }
            if (n1 < HH) {
                float h = __uint_as_float(hhi);
                hb2[n1 * 33 + lane] = dup2(h);
                if (WRITE_SEQ)
                    seq_out[((size_t)t * HH + n1) * BB + row0 + lane] = h;
                if (FINAL_OUT && t == TT - 1)
                    fin_out[n1 * BB + row0 + lane] = h;
            }
        }
        __syncthreads();   // hb2 / inb2 ready for next step
    }
}

// head: out = sigmoid(relu(h1 @ W1.T + b1) @ W2.T + b2)
__global__ void __launch_bounds__(256)
head_kernel(const float* __restrict__ h1,  // [H][B]
            const float* __restrict__ W1, const float* __restrict__ b1,
            const float* __restrict__ W2, const float* __restrict__ b2,
            float* __restrict__ out)
{
    __shared__ float sW1[50 * HH];
    __shared__ float sb1[50];
    __shared__ float sW2[50];
    __shared__ float sb2;
    for (int i = threadIdx.x; i < 50 * HH; i += 256) sW1[i] = W1[i];
    if (threadIdx.x < 50) {
        sb1[threadIdx.x] = b1[threadIdx.x];
        sW2[threadIdx.x] = W2[threadIdx.x];
    }
    if (threadIdx.x == 0) sb2 = b2[0];
    __syncthreads();

    int row = blockIdx.x * 256 + threadIdx.x;
    float h[HH];
#pragma unroll
    for (int n = 0; n < HH; n++) h[n] = h1[n * BB + row];

    float o = sb2;
    for (int s = 0; s < 50; s++) {
        float a = sb1[s];
#pragma unroll
        for (int n = 0; n < HH; n++) a += h[n] * sW1[s * HH + n];
        a = fmaxf(a, 0.f);
        o += a * sW2[s];
    }
    out[row] = fsigmoids(o);
}

extern "C" void kernel_launch(void* const* d_in, const int* in_sizes, int n_in,
                              void* d_out, int out_size)
{
    int o = (n_in >= 14 && in_sizes[1] == 1) ? 2 : 1;
    const float* data_in = (const float*)d_in[0];
    const float* W_ih0 = (const float*)d_in[o + 0];
    const float* W_hh0 = (const float*)d_in[o + 1];
    const float* b_ih0 = (const float*)d_in[o + 2];
    const float* b_hh0 = (const float*)d_in[o + 3];
    const float* W_ih1 = (const float*)d_in[o + 4];
    const float* W_hh1 = (const float*)d_in[o + 5];
    const float* b_ih1 = (const float*)d_in[o + 6];
    const float* b_hh1 = (const float*)d_in[o + 7];
    const float* W1    = (const float*)d_in[o + 8];
    const float* b1    = (const float*)d_in[o + 9];
    const float* W2    = (const float*)d_in[o + 10];
    const float* b2    = (const float*)d_in[o + 11];

    float *h0p = nullptr, *h1p = nullptr;
    cudaGetSymbolAddress((void**)&h0p, g_h0);
    cudaGetSymbolAddress((void**)&h1p, g_h1);

    const int sm0 = ((DD + HH) * GP + GP) * 4 + (DD * 33 + HH * 33) * 8;
    const int sm1 = ((HH + HH) * GP + GP) * 4 + (HH * 33 + HH * 33) * 8;

    cudaFuncSetAttribute((const void*)lstm_layer<DD, false, true, false>,
                         cudaFuncAttributeMaxDynamicSharedMemorySize, sm0);
    cudaFuncSetAttribute((const void*)lstm_layer<HH, true, false, true>,
                         cudaFuncAttributeMaxDynamicSharedMemorySize, sm1);

    lstm_layer<DD, false, true, false><<<NBLK, NTHR, sm0>>>(
        data_in, W_ih0, W_hh0, b_ih0, b_hh0, h0p, nullptr);
    lstm_layer<HH, true, false, true><<<NBLK, NTHR, sm1>>>(
        h0p, W_ih1, W_hh1, b_ih1, b_hh1, nullptr, h1p);
    head_kernel<<<BB / 256, 256>>>(h1p, W1, b1, W2, b2, (float*)d_out);
}